// round 1
// baseline (speedup 1.0000x reference)
#include <cuda_runtime.h>

// Problem constants (fixed by setup_inputs)
#define Bq 8
#define Cc 64
#define Hh 200
#define Ww 320
#define Nn 48
#define WD 80                       // W / STRIDE
static constexpr float FSTRIDE = 4.0f;   // pad_w / W = 1280 / 320
static constexpr float NEGV = -100000000.0f;

// Scratch (no allocation allowed): fused weights/bias per (b,n)
__device__ float g_W2[Bq * Nn * Cc];
__device__ float g_b2[Bq * Nn];

// ---------------------------------------------------------------------------
// Prep: per (b,n) compute
//   yc, idx, centers
//   kfm[c]   = mean_w kernel_feats[b,c,idx,w]
//   vk[o]    = bk[o] + sum_c Wk[o,c]*kfm[c]           (o in [0,64])
//   wgt = vk[0:64], bias = vk[64]
//   W2[c]    = sum_o wgt[o]*Wf[o,c]
//   b2       = sum_o wgt[o]*bf[o] + bias
// One block per (b,n), 128 threads.
// ---------------------------------------------------------------------------
__global__ void prep_kernel(const float* __restrict__ kf,
                            const float* __restrict__ Wk,
                            const float* __restrict__ bk,
                            const float* __restrict__ Wf,
                            const float* __restrict__ bf,
                            const float* __restrict__ db,
                            float* __restrict__ centers_out) {
    const int bn  = blockIdx.x;
    const int b   = bn / Nn;
    const int tid = threadIdx.x;

    __shared__ float kfm[Cc];
    __shared__ float sW[Cc];
    __shared__ float sBias;

    const float y1 = db[bn * 4 + 1];
    const float y2 = db[bn * 4 + 3];
    const float yc = (y1 + y2) / (2.0f * FSTRIDE);
    const int  idx = (int)yc;
    if (tid == 0) centers_out[bn] = yc * FSTRIDE;

    if (tid < Cc) {
        const float4* p4 = (const float4*)(kf +
            (((size_t)b * Cc + tid) * Hh + idx) * WD);
        float s = 0.0f;
        #pragma unroll
        for (int w = 0; w < WD / 4; w++) {
            float4 v = p4[w];
            s += v.x + v.y + v.z + v.w;
        }
        kfm[tid] = s * (1.0f / (float)WD);
    }
    __syncthreads();

    if (tid <= Cc) {  // 65 rows of Wk
        float acc = bk[tid];
        #pragma unroll 8
        for (int c = 0; c < Cc; c++) acc += Wk[tid * Cc + c] * kfm[c];
        if (tid < Cc) sW[tid] = acc; else sBias = acc;
    }
    __syncthreads();

    if (tid < Cc) {
        float acc = 0.0f;
        #pragma unroll 8
        for (int o = 0; o < Cc; o++) acc += sW[o] * Wf[o * Cc + tid];
        g_W2[bn * Cc + tid] = acc;
    } else if (tid == Cc) {
        float acc = sBias;
        for (int o = 0; o < Cc; o++) acc += sW[o] * bf[o];
        g_b2[bn] = acc;
    }
}

// ---------------------------------------------------------------------------
// Main: logits[b,n,h,w] = sum_c W2[b,n,c]*feats[b,c,h,w] + b2[b,n],
// masked to -1e8 where h >= hlim[b] or w >= wlim[b].
// Block = (b, h, 64-pixel w tile), 128 threads.
// Thread (ng 0..7, pg 0..15) computes 6 n-rows x 4 pixels.
// Fully-masked tiles take a pure fill path (no feats read, no FMA).
// ---------------------------------------------------------------------------
__global__ __launch_bounds__(128)
void main_kernel(const float* __restrict__ feats,
                 const int* __restrict__ imshape,
                 float* __restrict__ logits) {
    const int b   = blockIdx.z;
    const int h   = blockIdx.y;
    const int w0  = blockIdx.x * 64;
    const int tid = threadIdx.x;

    const int hlim = (int)((float)imshape[b * 2 + 1] / FSTRIDE);
    const int wlim = (int)((float)imshape[b * 2 + 0] / FSTRIDE);

    float* outbase = logits + ((size_t)b * Nn * Hh + h) * Ww + w0;

    if (h >= hlim || w0 >= wlim) {
        // fully masked tile: fill 48 n x 64 px with -1e8 (768 float4)
        const float4 fill = make_float4(NEGV, NEGV, NEGV, NEGV);
        #pragma unroll
        for (int k = 0; k < 6; k++) {
            int i = tid + k * 128;
            int n = i >> 4, q = i & 15;
            *(float4*)(outbase + (size_t)n * Hh * Ww + q * 4) = fill;
        }
        return;
    }

    __shared__ float W2s[Nn * 65];   // padded stride 65: kills bank conflicts
    __shared__ float Fs[Cc * 64];    // [c][pixel]

    // load fused weights for this batch (768 float4)
    const float4* w2g = (const float4*)(g_W2 + b * Nn * Cc);
    #pragma unroll
    for (int k = 0; k < 6; k++) {
        int i = tid + k * 128;
        int n = i >> 4, q = i & 15;
        float4 v = w2g[i];
        float* dst = &W2s[n * 65 + q * 4];
        dst[0] = v.x; dst[1] = v.y; dst[2] = v.z; dst[3] = v.w;
    }
    // load feats tile: 64 channels x 64 px (1024 float4)
    #pragma unroll
    for (int k = 0; k < 8; k++) {
        int i = tid + k * 128;
        int c = i >> 4, q = i & 15;
        const float4* src = (const float4*)(feats +
            (((size_t)b * Cc + c) * Hh + h) * Ww + w0);
        ((float4*)Fs)[i] = src[q];
    }
    __syncthreads();

    const int pg = tid & 15;    // pixel group: pixels pg*4 .. pg*4+3
    const int ng = tid >> 4;    // n group: n = ng*6 + j

    float acc[6][4];
    #pragma unroll
    for (int j = 0; j < 6; j++) {
        float b2v = g_b2[b * Nn + ng * 6 + j];
        #pragma unroll
        for (int i = 0; i < 4; i++) acc[j][i] = b2v;
    }

    #pragma unroll 8
    for (int c = 0; c < Cc; c++) {
        float4 fv = ((const float4*)Fs)[c * 16 + pg];
        #pragma unroll
        for (int j = 0; j < 6; j++) {
            float wv = W2s[(ng * 6 + j) * 65 + c];
            acc[j][0] += wv * fv.x;
            acc[j][1] += wv * fv.y;
            acc[j][2] += wv * fv.z;
            acc[j][3] += wv * fv.w;
        }
    }

    const int nvalid = wlim - w0;   // > 0 on this path
    const int px = pg * 4;
    #pragma unroll
    for (int j = 0; j < 6; j++) {
        const int n = ng * 6 + j;
        float4 v;
        v.x = (px + 0 < nvalid) ? acc[j][0] : NEGV;
        v.y = (px + 1 < nvalid) ? acc[j][1] : NEGV;
        v.z = (px + 2 < nvalid) ? acc[j][2] : NEGV;
        v.w = (px + 3 < nvalid) ? acc[j][3] : NEGV;
        *(float4*)(outbase + (size_t)n * Hh * Ww + px) = v;
    }
}

extern "C" void kernel_launch(void* const* d_in, const int* in_sizes, int n_in,
                              void* d_out, int out_size) {
    const float* feats   = (const float*)d_in[0];
    const float* kf      = (const float*)d_in[1];
    const float* Wk      = (const float*)d_in[2];
    const float* bk      = (const float*)d_in[3];
    const float* Wf      = (const float*)d_in[4];
    const float* bf      = (const float*)d_in[5];
    const float* db      = (const float*)d_in[6];
    const int*   imshape = (const int*)d_in[7];

    float* logits  = (float*)d_out;
    float* centers = logits + (size_t)Bq * Nn * Hh * Ww;

    prep_kernel<<<Bq * Nn, 128>>>(kf, Wk, bk, Wf, bf, db, centers);
    main_kernel<<<dim3(Ww / 64, Hh, Bq), 128>>>(feats, imshape, logits);
}

// round 2
// speedup vs baseline: 1.2557x; 1.2557x over previous
#include <cuda_runtime.h>

// Problem constants (fixed by setup_inputs)
#define Bq 8
#define Cc 64
#define Hh 200
#define Ww 320
#define Nn 48
#define WD 80                       // W / STRIDE
static constexpr float FSTRIDE = 4.0f;   // pad_w / W = 1280 / 320
static constexpr float NEGV = -100000000.0f;

#define W2STRIDE 68                 // padded, float4-aligned, conflict-free

// Scratch (no allocation allowed): fused weights/bias per (b,n)
__device__ float g_W2[Bq * Nn * Cc];
__device__ float g_b2[Bq * Nn];

// ---- packed f32x2 helpers (FFMA2 path, PTX-only) ---------------------------
__device__ __forceinline__ unsigned long long pack_dup(float w) {
    unsigned long long r;
    asm("mov.b64 %0, {%1, %1};" : "=l"(r) : "f"(w));
    return r;
}
__device__ __forceinline__ unsigned long long pack2(float a, float b) {
    unsigned long long r;
    asm("mov.b64 %0, {%1, %2};" : "=l"(r) : "f"(a), "f"(b));
    return r;
}
__device__ __forceinline__ void fma2(unsigned long long& acc,
                                     unsigned long long a,
                                     unsigned long long b) {
    asm("fma.rn.f32x2 %0, %1, %2, %0;" : "+l"(acc) : "l"(a), "l"(b));
}
__device__ __forceinline__ float2 unpack2(unsigned long long v) {
    float2 r;
    asm("mov.b64 {%0, %1}, %2;" : "=f"(r.x), "=f"(r.y) : "l"(v));
    return r;
}

// ---------------------------------------------------------------------------
// Prep: per (b,n):
//   kfm[c] = mean_w kernel_feats[b,c,idx,w]
//   vk[o]  = bk[o] + Wk[o,:]·kfm ;  wgt=vk[0:64], bias=vk[64]
//   W2[c]  = wgt·Wf[:,c] ;  b2 = wgt·bf + bias
// One block per (b,n), 128 threads (2 threads per channel in the mean).
// ---------------------------------------------------------------------------
__global__ void prep_kernel(const float* __restrict__ kf,
                            const float* __restrict__ Wk,
                            const float* __restrict__ bk,
                            const float* __restrict__ Wf,
                            const float* __restrict__ bf,
                            const float* __restrict__ db,
                            float* __restrict__ centers_out) {
    const int bn  = blockIdx.x;
    const int b   = bn / Nn;
    const int tid = threadIdx.x;

    __shared__ float kfm[Cc];
    __shared__ float sW[Cc];
    __shared__ float sBias;

    const float y1 = db[bn * 4 + 1];
    const float y2 = db[bn * 4 + 3];
    const float yc = (y1 + y2) / (2.0f * FSTRIDE);
    const int  idx = (int)yc;
    if (tid == 0) centers_out[bn] = yc * FSTRIDE;

    {   // 2 threads per channel, 10 float4 each, combine via shfl
        const int c    = tid >> 1;
        const int half = tid & 1;
        const float4* p4 = (const float4*)(kf +
            (((size_t)b * Cc + c) * Hh + idx) * WD) + half * 10;
        float s = 0.0f;
        #pragma unroll
        for (int w = 0; w < 10; w++) {
            float4 v = p4[w];
            s += v.x + v.y + v.z + v.w;
        }
        s += __shfl_xor_sync(0xFFFFFFFFu, s, 1);
        if (half == 0) kfm[c] = s * (1.0f / (float)WD);
    }
    __syncthreads();

    if (tid <= Cc) {  // 65 rows of Wk
        float acc = bk[tid];
        const float4* wrow = (const float4*)(Wk + tid * Cc);
        #pragma unroll
        for (int c = 0; c < Cc / 4; c++) {
            float4 v = wrow[c];
            acc += v.x * kfm[c * 4 + 0] + v.y * kfm[c * 4 + 1]
                 + v.z * kfm[c * 4 + 2] + v.w * kfm[c * 4 + 3];
        }
        if (tid < Cc) sW[tid] = acc; else sBias = acc;
    }
    __syncthreads();

    if (tid < Cc) {
        float acc = 0.0f;
        #pragma unroll 16
        for (int o = 0; o < Cc; o++) acc += sW[o] * Wf[o * Cc + tid];
        g_W2[bn * Cc + tid] = acc;
    } else if (tid == Cc) {
        float acc = sBias;
        for (int o = 0; o < Cc; o++) acc += sW[o] * bf[o];
        g_b2[bn] = acc;
    }
}

// ---------------------------------------------------------------------------
// Main: logits[b,n,h,w] = W2[b,n,:]·feats[b,:,h,w] + b2[b,n], masked.
// Block = (b, h, 64-px w tile), 128 threads; thread = 6 n-rows x 4 pixels.
// Inner loop: c in steps of 4, float4 weight loads, packed f32x2 FMAs.
// ---------------------------------------------------------------------------
__global__ __launch_bounds__(128)
void main_kernel(const float* __restrict__ feats,
                 const int* __restrict__ imshape,
                 float* __restrict__ logits) {
    const int b   = blockIdx.z;
    const int h   = blockIdx.y;
    const int w0  = blockIdx.x * 64;
    const int tid = threadIdx.x;

    const int hlim = (int)((float)imshape[b * 2 + 1] / FSTRIDE);
    const int wlim = (int)((float)imshape[b * 2 + 0] / FSTRIDE);

    float* outbase = logits + ((size_t)b * Nn * Hh + h) * Ww + w0;

    if (h >= hlim || w0 >= wlim) {
        const float4 fill = make_float4(NEGV, NEGV, NEGV, NEGV);
        #pragma unroll
        for (int k = 0; k < 6; k++) {
            int i = tid + k * 128;
            int n = i >> 4, q = i & 15;
            *(float4*)(outbase + (size_t)n * Hh * Ww + q * 4) = fill;
        }
        return;
    }

    __shared__ float W2s[Nn * W2STRIDE];   // stride 68: float4 aligned rows
    __shared__ float Fs[Cc * 64];          // [c][pixel]

    // load fused weights (48 rows x 16 float4)
    {
        const float4* w2g = (const float4*)(g_W2 + b * Nn * Cc);
        #pragma unroll
        for (int k = 0; k < 6; k++) {
            int i = tid + k * 128;
            int n = i >> 4, q = i & 15;
            *(float4*)&W2s[n * W2STRIDE + q * 4] = w2g[i];
        }
    }
    // load feats tile: 64 channels x 64 px (1024 float4)
    #pragma unroll
    for (int k = 0; k < 8; k++) {
        int i = tid + k * 128;
        int c = i >> 4, q = i & 15;
        const float4* src = (const float4*)(feats +
            (((size_t)b * Cc + c) * Hh + h) * Ww + w0);
        ((float4*)Fs)[i] = src[q];
    }
    __syncthreads();

    const int pg = tid & 15;    // pixels pg*4 .. pg*4+3
    const int ng = tid >> 4;    // n = ng*6 + j

    // accumulators: 6 n-rows x 2 pixel-pairs, packed f32x2
    unsigned long long acc[6][2];
    #pragma unroll
    for (int j = 0; j < 6; j++) {
        float b2v = g_b2[b * Nn + ng * 6 + j];
        acc[j][0] = pack_dup(b2v);
        acc[j][1] = acc[j][0];
    }

    const float4* Fs4  = (const float4*)Fs;
    #pragma unroll 2
    for (int c4 = 0; c4 < Cc / 4; c4++) {
        // 4 pixel float4s for channels c4*4..c4*4+3 -> 8 packed pairs
        unsigned long long fp[4][2];
        #pragma unroll
        for (int cc = 0; cc < 4; cc++) {
            float4 fv = Fs4[(c4 * 4 + cc) * 16 + pg];
            fp[cc][0] = pack2(fv.x, fv.y);
            fp[cc][1] = pack2(fv.z, fv.w);
        }
        #pragma unroll
        for (int j = 0; j < 6; j++) {
            float4 w4 = *(const float4*)&W2s[(ng * 6 + j) * W2STRIDE + c4 * 4];
            unsigned long long wp;
            wp = pack_dup(w4.x); fma2(acc[j][0], fp[0][0], wp); fma2(acc[j][1], fp[0][1], wp);
            wp = pack_dup(w4.y); fma2(acc[j][0], fp[1][0], wp); fma2(acc[j][1], fp[1][1], wp);
            wp = pack_dup(w4.z); fma2(acc[j][0], fp[2][0], wp); fma2(acc[j][1], fp[2][1], wp);
            wp = pack_dup(w4.w); fma2(acc[j][0], fp[3][0], wp); fma2(acc[j][1], fp[3][1], wp);
        }
    }

    const int nvalid = wlim - w0;   // > 0 on this path
    const int px = pg * 4;
    #pragma unroll
    for (int j = 0; j < 6; j++) {
        const int n = ng * 6 + j;
        float2 lo = unpack2(acc[j][0]);
        float2 hi = unpack2(acc[j][1]);
        float4 v;
        v.x = (px + 0 < nvalid) ? lo.x : NEGV;
        v.y = (px + 1 < nvalid) ? lo.y : NEGV;
        v.z = (px + 2 < nvalid) ? hi.x : NEGV;
        v.w = (px + 3 < nvalid) ? hi.y : NEGV;
        *(float4*)(outbase + (size_t)n * Hh * Ww + px) = v;
    }
}

extern "C" void kernel_launch(void* const* d_in, const int* in_sizes, int n_in,
                              void* d_out, int out_size) {
    const float* feats   = (const float*)d_in[0];
    const float* kf      = (const float*)d_in[1];
    const float* Wk      = (const float*)d_in[2];
    const float* bk      = (const float*)d_in[3];
    const float* Wf      = (const float*)d_in[4];
    const float* bf      = (const float*)d_in[5];
    const float* db      = (const float*)d_in[6];
    const int*   imshape = (const int*)d_in[7];

    float* logits  = (float*)d_out;
    float* centers = logits + (size_t)Bq * Nn * Hh * Ww;

    prep_kernel<<<Bq * Nn, 128>>>(kf, Wk, bk, Wf, bf, db, centers);
    main_kernel<<<dim3(Ww / 64, Hh, Bq), 128>>>(feats, imshape, logits);
}